// round 11
// baseline (speedup 1.0000x reference)
#include <cuda_runtime.h>
#include <cuda_bf16.h>
#include <cstdint>

#define NS 128
#define NA 32
#define NB 64
#define NT 4096

#define NC    64           // chunks per batch
#define SPAN  64           // logged steps per chunk (multiple of 8)
#define WARM  32           // warmup steps (multiple of 8)

// alpha SMEM layout (bf16x2 words): word addr = 80*row + 20*q + idx
// (row 0..31, q = lane&3, idx 0..15; pair index pi = 4*idx + q).

__global__ void zero_out(float* out) { out[threadIdx.x] = 0.0f; }

__device__ __forceinline__ unsigned pack_bf(float lo, float hi) {
    unsigned d;
    asm("cvt.rn.bf16x2.f32 %0, %1, %2;" : "=r"(d) : "f"(hi), "f"(lo));
    return d;
}

__device__ __forceinline__ void mma16816(
    float& c0, float& c1, float& c2, float& c3,
    unsigned a0, unsigned a1, unsigned a2, unsigned a3,
    unsigned b0, unsigned b1)
{
    asm volatile(
        "mma.sync.aligned.m16n8k16.row.col.f32.bf16.bf16.f32 "
        "{%0,%1,%2,%3}, {%4,%5,%6,%7}, {%8,%9}, {%0,%1,%2,%3};"
        : "+f"(c0), "+f"(c1), "+f"(c2), "+f"(c3)
        : "r"(a0), "r"(a1), "r"(a2), "r"(a3), "r"(b0), "r"(b1));
}

// grid = NC*2 = 128 CTAs, 256 threads (8 warps).
// CTA: chunk c = blockIdx>>1, batch group bg = blockIdx&1 -> 32 streams
// (batches bg*32 .. bg*32+31) as two MMA m-tiles (rows 0-15, 16-31).
// Warp w owns n-states [16w, 16w+16) = 2 n-tiles; per step: 2 m-tiles x
// 2 n-tiles x 8 kt = 32 HMMA in 4 independent accumulation chains.
// chunk 0: exact init at t=0. chunk c>0: uniform init WARM steps early; the
// final warmup renorm lands on t = c*SPAN-1 (global cadence-aligned) so the
// logged renorm sums match the exact chain (validated R7-R10).
__global__ void __launch_bounds__(256)
hmm_fwd(const float* __restrict__ inputs,
        const float* __restrict__ Al,
        const float* __restrict__ Bl,
        const float* __restrict__ Il,
        float* __restrict__ out) {
    const int tid  = threadIdx.x;
    const int w    = tid >> 5;
    const int lane = tid & 31;
    const int g    = lane >> 2;   // 0..7  (mma group)
    const int q    = lane & 3;    // 0..3  (thread-in-group)
    const int c    = blockIdx.x >> 1;
    const int bg   = blockIdx.x & 1;

    const int tokBase  = c * SPAN - (c ? WARM : 0);
    const int tStart   = tokBase + 1;
    const int tEnd     = (c + 1) * SPAN;     // exclusive
    const int logStart = c * SPAN;
    const int tokCnt   = tEnd - tokBase;     // 64 or 96

    __shared__ float sB[NA * 132];                  // emissions, padded rows
    __shared__ unsigned char sTok[32][96];
    __shared__ __align__(16) unsigned sAF[2][2560]; // alpha bf16x2, permuted
    __shared__ float sPart[8][32];
    __shared__ float sS[32];
    __shared__ float sMaxA[NS], sInvA[NS], sI[NS];

    // ---- prep: softmax stats (threads 0..127) ----
    if (tid < NS) {
        {   // A row softmax stats (axis 1)
            const float* rp = Al + tid * NS;
            float m = -1e30f;
            for (int k = 0; k < NS; k += 4) {
                float4 v = *(const float4*)(rp + k);
                m = fmaxf(m, fmaxf(fmaxf(v.x, v.y), fmaxf(v.z, v.w)));
            }
            float s = 0.f;
            for (int k = 0; k < NS; k += 4) {
                float4 v = *(const float4*)(rp + k);
                s += __expf(v.x - m) + __expf(v.y - m) + __expf(v.z - m) + __expf(v.w - m);
            }
            sMaxA[tid] = m;
            sInvA[tid] = 1.f / s;
        }
        {   // I softmax
            float m = -1e30f;
            for (int k = 0; k < NS; k++) m = fmaxf(m, Il[k]);
            float s = 0.f;
            for (int k = 0; k < NS; k++) s += __expf(Il[k] - m);
            sI[tid] = __expf(Il[tid] - m) / s;
        }
        {   // B softmax over alphabet, state column tid
            float m = -1e30f;
            for (int a = 0; a < NA; a++) m = fmaxf(m, Bl[a * NS + tid]);
            float s = 0.f;
            for (int a = 0; a < NA; a++) s += __expf(Bl[a * NS + tid] - m);
            float inv = 1.f / s;
            for (int a = 0; a < NA; a++)
                sB[a * 132 + tid] = __expf(Bl[a * NS + tid] - m) * inv;
        }
    }
    // tokens: 32 streams x tokCnt
    for (int r = 0; r < 32; r++) {
        const float* base = inputs + ((size_t)(bg * 32 + r) * NT + tokBase) * NA;
        for (int n = tid; n < tokCnt; n += 256) {
            const float4* p = (const float4*)(base + (size_t)n * NA);
            float tk = 0.f;
#pragma unroll
            for (int k = 0; k < 8; k++) {
                float4 v = p[k];
                tk += v.x * (float)(4 * k) + v.y * (float)(4 * k + 1) +
                      v.z * (float)(4 * k + 2) + v.w * (float)(4 * k + 3);
            }
            sTok[r][n] = (unsigned char)(int)(tk + 0.5f);
        }
    }
    __syncthreads();

    // ---- B-fragments: transition matrix for this warp's 2 n-tiles ----
    unsigned Bf[2][8][2];
#pragma unroll
    for (int i = 0; i < 2; i++) {
        int n = (2 * w + i) * 8 + g;
#pragma unroll
        for (int kt = 0; kt < 8; kt++) {
            int k0 = 16 * kt + 2 * q;
            float a00 = __expf(Al[k0 * NS + n] - sMaxA[k0]) * sInvA[k0];
            float a01 = __expf(Al[(k0 + 1) * NS + n] - sMaxA[k0 + 1]) * sInvA[k0 + 1];
            Bf[i][kt][0] = pack_bf(a00, a01);
            int k1 = k0 + 8;
            float a10 = __expf(Al[k1 * NS + n] - sMaxA[k1]) * sInvA[k1];
            float a11 = __expf(Al[(k1 + 1) * NS + n] - sMaxA[k1 + 1]) * sInvA[k1 + 1];
            Bf[i][kt][1] = pack_bf(a10, a11);
        }
    }

    // ---- init alpha at t = tokBase into buffer 0 ----
    for (int idx = tid; idx < 32 * 64; idx += 256) {
        int row = idx >> 6, pi = idx & 63;
        int n = 2 * pi;
        float v0, v1;
        if (c == 0) {
            int tk = sTok[row][0];
            v0 = sI[n] * sB[tk * 132 + n];
            v1 = sI[n + 1] * sB[tk * 132 + n + 1];
        } else {
            v0 = v1 = 1.0f;   // uniform direction; contraction fixes it
        }
        sAF[0][80 * row + 20 * (pi & 3) + (pi >> 2)] = pack_bf(v0, v1);
    }
    __syncthreads();

    float ll = 0.0f;   // stream loglik, owned by threads tid<32

    auto step = [&](int t, const unsigned* rd, unsigned* wr) {
        int tt = t - tokBase;
        // tokens for this thread's 4 rows
        int tok[2][2];
        tok[0][0] = sTok[g][tt];      tok[0][1] = sTok[g + 8][tt];
        tok[1][0] = sTok[g + 16][tt]; tok[1][1] = sTok[g + 24][tt];

        // stage alpha slices: 4 rows x 4 uint4 (idx 0..15, phase q)
        unsigned wA[2][2][16];
#pragma unroll
        for (int mt = 0; mt < 2; mt++) {
#pragma unroll
            for (int rr = 0; rr < 2; rr++) {
                const uint4* p = (const uint4*)(rd + 80 * (g + 8 * rr + 16 * mt) + 20 * q);
#pragma unroll
                for (int m = 0; m < 4; m++) {
                    uint4 u = p[m];
                    wA[mt][rr][4 * m]     = u.x;
                    wA[mt][rr][4 * m + 1] = u.y;
                    wA[mt][rr][4 * m + 2] = u.z;
                    wA[mt][rr][4 * m + 3] = u.w;
                }
            }
        }

        float acc[2][2][4];
#pragma unroll
        for (int mt = 0; mt < 2; mt++)
#pragma unroll
            for (int i = 0; i < 2; i++)
#pragma unroll
                for (int x = 0; x < 4; x++) acc[mt][i][x] = 0.f;

#pragma unroll
        for (int kt = 0; kt < 8; kt++) {
#pragma unroll
            for (int mt = 0; mt < 2; mt++) {
                unsigned a0 = wA[mt][0][2 * kt], a2 = wA[mt][0][2 * kt + 1];
                unsigned a1 = wA[mt][1][2 * kt], a3 = wA[mt][1][2 * kt + 1];
                mma16816(acc[mt][0][0], acc[mt][0][1], acc[mt][0][2], acc[mt][0][3],
                         a0, a1, a2, a3, Bf[0][kt][0], Bf[0][kt][1]);
                mma16816(acc[mt][1][0], acc[mt][1][1], acc[mt][1][2], acc[mt][1][3],
                         a0, a1, a2, a3, Bf[1][kt][0], Bf[1][kt][1]);
            }
        }

        // emission multiply
        float v[2][2][4];
#pragma unroll
        for (int mt = 0; mt < 2; mt++) {
#pragma unroll
            for (int i = 0; i < 2; i++) {
                int n = (2 * w + i) * 8 + 2 * q;
                float2 e0 = *(const float2*)(sB + tok[mt][0] * 132 + n);
                float2 e1 = *(const float2*)(sB + tok[mt][1] * 132 + n);
                v[mt][i][0] = acc[mt][i][0] * e0.x;
                v[mt][i][1] = acc[mt][i][1] * e0.y;
                v[mt][i][2] = acc[mt][i][2] * e1.x;
                v[mt][i][3] = acc[mt][i][3] * e1.y;
            }
        }

        if ((t & 7) == 7) {  // renormalize every 8 steps (aligned cadence)
#pragma unroll
            for (int mt = 0; mt < 2; mt++) {
                float s0 = (v[mt][0][0] + v[mt][0][1]) + (v[mt][1][0] + v[mt][1][1]);
                float s1 = (v[mt][0][2] + v[mt][0][3]) + (v[mt][1][2] + v[mt][1][3]);
                s0 += __shfl_xor_sync(0xffffffffu, s0, 1);
                s0 += __shfl_xor_sync(0xffffffffu, s0, 2);
                s1 += __shfl_xor_sync(0xffffffffu, s1, 1);
                s1 += __shfl_xor_sync(0xffffffffu, s1, 2);
                if (q == 0) {
                    sPart[w][g + 16 * mt]     = s0;
                    sPart[w][g + 8 + 16 * mt] = s1;
                }
            }
            __syncthreads();
            if (tid < 32) {
                float S = 0.f;
#pragma unroll
                for (int ww = 0; ww < 8; ww++) S += sPart[ww][tid];
                sS[tid] = S;
                if (t >= logStart) ll += __logf(S);
            }
            __syncthreads();
#pragma unroll
            for (int mt = 0; mt < 2; mt++) {
                float i0 = __fdividef(1.0f, sS[g + 16 * mt]);
                float i1 = __fdividef(1.0f, sS[g + 8 + 16 * mt]);
#pragma unroll
                for (int i = 0; i < 2; i++) {
                    v[mt][i][0] *= i0; v[mt][i][1] *= i0;
                    v[mt][i][2] *= i1; v[mt][i][3] *= i1;
                }
            }
        }

        // pack + write 4 rows (n-tile pair -> consecutive idx 2w, 2w+1)
#pragma unroll
        for (int mt = 0; mt < 2; mt++) {
            uint2 o0, o1;
            o0.x = pack_bf(v[mt][0][0], v[mt][0][1]);
            o0.y = pack_bf(v[mt][1][0], v[mt][1][1]);
            o1.x = pack_bf(v[mt][0][2], v[mt][0][3]);
            o1.y = pack_bf(v[mt][1][2], v[mt][1][3]);
            *(uint2*)(wr + 80 * (g + 16 * mt) + 20 * q + 2 * w) = o0;
            *(uint2*)(wr + 80 * (g + 8 + 16 * mt) + 20 * q + 2 * w) = o1;
        }
        __syncthreads();
    };

    unsigned* B0 = sAF[0];
    unsigned* B1 = sAF[1];

    // step counts: 63 (c==0) or 95 (c>0) -> odd for both
    step(tStart, B0, B1);
    for (int t = tStart + 1; t < tEnd; t += 2) {
        step(t, B1, B0);
        step(t + 1, B0, B1);
    }

    if (tid < 32) atomicAdd(&out[bg * 32 + tid], ll);
}

// ---------------- launch ----------------
extern "C" void kernel_launch(void* const* d_in, const int* in_sizes, int n_in,
                              void* d_out, int out_size) {
    const float* inputs = nullptr;   // 64*4096*32 = 8388608
    const float* A_logits = nullptr; // 128*128    = 16384
    const float* B_logits = nullptr; // 32*128     = 4096
    const float* I_logits = nullptr; // 128
    for (int i = 0; i < n_in; i++) {
        switch (in_sizes[i]) {
            case NB * NT * NA: inputs = (const float*)d_in[i]; break;
            case NS * NS:      A_logits = (const float*)d_in[i]; break;
            case NA * NS:      B_logits = (const float*)d_in[i]; break;
            case NS:           I_logits = (const float*)d_in[i]; break;
        }
    }
    float* out = (float*)d_out;
    zero_out<<<1, NB>>>(out);
    hmm_fwd<<<NC * 2, 256>>>(inputs, A_logits, B_logits, I_logits, out);
}